// round 2
// baseline (speedup 1.0000x reference)
#include <cuda_runtime.h>
#include <cuda_bf16.h>
#include <cstdint>

#define NROW 4096
#define ZD   2048
#define TWO_N 8192
#define TM_TILE 128
#define TN_TILE 128
#define TK 32
#define NKS (ZD / TK)          // 64 k-stages
#define STAGES 4
#define STAGE_BYTES (TM_TILE * 64 * 2)   // A(8KB) + B(8KB)
#define SMEM_TOTAL (STAGES * STAGE_BYTES) // 64 KB dynamic

// ---------------- scratch (device globals; no allocation allowed) ----------
__device__ __align__(256) __nv_bfloat16 g_reps[(size_t)TWO_N * ZD];   // 32 MB
__device__ float g_rowsum[TWO_N];
__device__ float g_pos[NROW];

// ---------------- helpers ---------------------------------------------------
__device__ __forceinline__ uint32_t smem_u32(const void* p) {
    uint32_t a;
    asm("{ .reg .u64 t; cvta.to.shared.u64 t, %1; cvt.u32.u64 %0, t; }" : "=r"(a) : "l"(p));
    return a;
}
#define CP_ASYNC16(dst, src) \
    asm volatile("cp.async.cg.shared.global [%0], [%1], 16;" :: "r"(dst), "l"(src))
#define CP_COMMIT() asm volatile("cp.async.commit_group;" ::: "memory")
#define CP_WAIT3()  asm volatile("cp.async.wait_group 3;" ::: "memory")

__device__ __forceinline__ void ldmatrix_x4(uint32_t& r0, uint32_t& r1,
                                            uint32_t& r2, uint32_t& r3, uint32_t addr) {
    asm volatile("ldmatrix.sync.aligned.m8n8.x4.shared.b16 {%0,%1,%2,%3}, [%4];"
                 : "=r"(r0), "=r"(r1), "=r"(r2), "=r"(r3) : "r"(addr));
}
__device__ __forceinline__ void mma_bf16(float* c, const uint32_t* a, uint32_t b0, uint32_t b1) {
    asm volatile("mma.sync.aligned.m16n8k16.row.col.f32.bf16.bf16.f32 "
                 "{%0,%1,%2,%3}, {%4,%5,%6,%7}, {%8,%9}, {%0,%1,%2,%3};"
                 : "+f"(c[0]), "+f"(c[1]), "+f"(c[2]), "+f"(c[3])
                 : "r"(a[0]), "r"(a[1]), "r"(a[2]), "r"(a[3]), "r"(b0), "r"(b1));
}

// ---------------- kernel 1: normalize + pos + zero rowsum ------------------
__global__ void __launch_bounds__(256) k_prep(const float* __restrict__ z1,
                                              const float* __restrict__ z2) {
    int row = blockIdx.x;
    int t = threadIdx.x, lane = t & 31, wid = t >> 5;
    const float4* p1 = reinterpret_cast<const float4*>(z1) + (size_t)row * (ZD / 4);
    const float4* p2 = reinterpret_cast<const float4*>(z2) + (size_t)row * (ZD / 4);
    float4 a[2], b[2];
    a[0] = p1[2 * t]; a[1] = p1[2 * t + 1];
    b[0] = p2[2 * t]; b[1] = p2[2 * t + 1];
    const float* af = reinterpret_cast<const float*>(a);
    const float* bf = reinterpret_cast<const float*>(b);
    float s1 = 0.f, s2 = 0.f, sd = 0.f;
    #pragma unroll
    for (int i = 0; i < 8; i++) { s1 += af[i] * af[i]; s2 += bf[i] * bf[i]; sd += af[i] * bf[i]; }
    #pragma unroll
    for (int o = 16; o > 0; o >>= 1) {
        s1 += __shfl_xor_sync(0xFFFFFFFF, s1, o);
        s2 += __shfl_xor_sync(0xFFFFFFFF, s2, o);
        sd += __shfl_xor_sync(0xFFFFFFFF, sd, o);
    }
    __shared__ float red[3][8];
    if (lane == 0) { red[0][wid] = s1; red[1][wid] = s2; red[2][wid] = sd; }
    __syncthreads();
    float t1 = 0.f, t2 = 0.f, td = 0.f;
    #pragma unroll
    for (int w = 0; w < 8; w++) { t1 += red[0][w]; t2 += red[1][w]; td += red[2][w]; }
    float r1 = rsqrtf(t1), r2 = rsqrtf(t2);
    if (t == 0) {
        g_pos[row] = td * r1 * r2 * 2.0f;   // /T, T=0.5
        g_rowsum[row] = 0.f;
        g_rowsum[row + NROW] = 0.f;
    }
    __nv_bfloat16 oa[8], ob[8];
    #pragma unroll
    for (int i = 0; i < 8; i++) { oa[i] = __float2bfloat16(af[i] * r1); ob[i] = __float2bfloat16(bf[i] * r2); }
    *reinterpret_cast<uint4*>(g_reps + (size_t)row * ZD + 8 * t)          = *reinterpret_cast<uint4*>(oa);
    *reinterpret_cast<uint4*>(g_reps + (size_t)(row + NROW) * ZD + 8 * t) = *reinterpret_cast<uint4*>(ob);
}

// ---------------- kernel 2: HMMA GEMM (upper triangle) + exp-reduce --------
__global__ void __launch_bounds__(256, 2) k_gemm() {
    const int tn = blockIdx.x, tm = blockIdx.y;
    if (tn < tm) return;                      // upper triangle only
    const bool diag = (tn == tm);

    extern __shared__ unsigned char smem[];
    uint32_t smem_base = smem_u32(smem);
    const int tid = threadIdx.x, lane = tid & 31, wid = tid >> 5;
    const int wm = wid & 1, wn = wid >> 1;    // warp grid 2 (M) x 4 (N)

    // global tile bases
    const __nv_bfloat16* gA = g_reps + (size_t)(tm * TM_TILE) * ZD;
    const __nv_bfloat16* gB = g_reps + (size_t)(tn * TN_TILE) * ZD;

    // per-thread cp.async assignment: 2 chunks each for A and B per stage
    const int idx0 = tid, idx1 = tid + 256;   // 0..511: row = idx>>2, chunk = idx&3
    const int r0 = idx0 >> 2, c0_ = idx0 & 3;
    const int r1 = idx1 >> 2, c1_ = idx1 & 3;
    const uint32_t so0 = r0 * 64 + ((c0_ ^ (r0 & 3)) << 4);
    const uint32_t so1 = r1 * 64 + ((c1_ ^ (r1 & 3)) << 4);

    auto load_stage = [&](int s, int ks) {
        uint32_t sa = smem_base + s * STAGE_BYTES;
        const __nv_bfloat16* a0 = gA + (size_t)r0 * ZD + ks * TK + c0_ * 8;
        const __nv_bfloat16* a1 = gA + (size_t)r1 * ZD + ks * TK + c1_ * 8;
        const __nv_bfloat16* b0 = gB + (size_t)r0 * ZD + ks * TK + c0_ * 8;
        const __nv_bfloat16* b1 = gB + (size_t)r1 * ZD + ks * TK + c1_ * 8;
        CP_ASYNC16(sa + so0, a0);
        CP_ASYNC16(sa + so1, a1);
        CP_ASYNC16(sa + 8192 + so0, b0);
        CP_ASYNC16(sa + 8192 + so1, b1);
    };

    float acc[4][4][4];
    #pragma unroll
    for (int i = 0; i < 4; i++)
        #pragma unroll
        for (int j = 0; j < 4; j++)
            #pragma unroll
            for (int q = 0; q < 4; q++) acc[i][j][q] = 0.f;

    // prefetch stages 0..2
    #pragma unroll
    for (int s = 0; s < 3; s++) { load_stage(s, s); CP_COMMIT(); }

    // ldmatrix lane addressing pieces
    const int lrow = lane & 15;               // row within 16
    const int lk   = lane >> 4;               // 0/1 -> k chunk select

    for (int ks = 0; ks < NKS; ks++) {
        if (ks + 3 < NKS) load_stage((ks + 3) & (STAGES - 1), ks + 3);
        CP_COMMIT();
        CP_WAIT3();
        __syncthreads();

        uint32_t sa = smem_base + (ks & (STAGES - 1)) * STAGE_BYTES;
        uint32_t sb = sa + 8192;

        #pragma unroll
        for (int k16 = 0; k16 < 2; k16++) {
            const int cbase = k16 * 2;
            uint32_t afr[4][4];
            #pragma unroll
            for (int i = 0; i < 4; i++) {
                int row = wm * 64 + i * 16 + lrow;
                int ch = (cbase + lk) ^ (row & 3);
                ldmatrix_x4(afr[i][0], afr[i][1], afr[i][2], afr[i][3],
                            sa + row * 64 + (ch << 4));
            }
            uint32_t bfr[2][4];
            #pragma unroll
            for (int h = 0; h < 2; h++) {
                int row = wn * 32 + h * 16 + lrow;
                int ch = (cbase + lk) ^ (row & 3);
                ldmatrix_x4(bfr[h][0], bfr[h][1], bfr[h][2], bfr[h][3],
                            sb + row * 64 + (ch << 4));
            }
            #pragma unroll
            for (int i = 0; i < 4; i++) {
                #pragma unroll
                for (int j = 0; j < 4; j++) {
                    uint32_t b0 = bfr[j >> 1][j & 1];
                    uint32_t b1 = bfr[j >> 1][(j & 1) + 2];
                    mma_bf16(acc[i][j], afr[i], b0, b1);
                }
            }
        }
        __syncthreads();
    }

    // ---------------- epilogue: exp(2s), mask diag, row+col reduce ----------
    const int rowbase = tm * TM_TILE + wm * 64;
    const int colbase = tn * TN_TILE + wn * 32;
    float rsum[4][2];
    float csum[4][2];
    #pragma unroll
    for (int i = 0; i < 4; i++) { rsum[i][0] = 0.f; rsum[i][1] = 0.f; }
    #pragma unroll
    for (int j = 0; j < 4; j++) { csum[j][0] = 0.f; csum[j][1] = 0.f; }

    #pragma unroll
    for (int i = 0; i < 4; i++) {
        #pragma unroll
        for (int j = 0; j < 4; j++) {
            #pragma unroll
            for (int q = 0; q < 4; q++) {
                int h = q >> 1, c = q & 1;
                float e = __expf(2.0f * acc[i][j][q]);   // logits = s / T, T=0.5
                if (diag) {
                    int grow = rowbase + i * 16 + (lane >> 2) + h * 8;
                    int gcol = colbase + j * 8 + (lane & 3) * 2 + c;
                    if (grow == gcol) e = 0.f;
                }
                rsum[i][h] += e;
                csum[j][c] += e;
            }
        }
    }
    // row reduce: lanes sharing (lane>>2) hold different cols -> xor 1,2
    #pragma unroll
    for (int i = 0; i < 4; i++) {
        #pragma unroll
        for (int h = 0; h < 2; h++) {
            float v = rsum[i][h];
            v += __shfl_xor_sync(0xFFFFFFFF, v, 1);
            v += __shfl_xor_sync(0xFFFFFFFF, v, 2);
            if ((lane & 3) == 0)
                atomicAdd(&g_rowsum[rowbase + i * 16 + (lane >> 2) + h * 8], v);
        }
    }
    // col reduce (symmetric contribution), off-diagonal tiles only
    if (!diag) {
        #pragma unroll
        for (int j = 0; j < 4; j++) {
            #pragma unroll
            for (int c = 0; c < 2; c++) {
                float v = csum[j][c];
                v += __shfl_xor_sync(0xFFFFFFFF, v, 4);
                v += __shfl_xor_sync(0xFFFFFFFF, v, 8);
                v += __shfl_xor_sync(0xFFFFFFFF, v, 16);
                if (lane < 4)
                    atomicAdd(&g_rowsum[colbase + j * 8 + lane * 2 + c], v);
            }
        }
    }
}

// ---------------- kernel 3: final reduction --------------------------------
__global__ void __launch_bounds__(256) k_final(float* __restrict__ out) {
    int t = threadIdx.x, lane = t & 31, wid = t >> 5;
    float acc = 0.f;
    for (int r = t; r < TWO_N; r += 256)
        acc += logf(g_rowsum[r]) - g_pos[r & (NROW - 1)];
    #pragma unroll
    for (int o = 16; o > 0; o >>= 1) acc += __shfl_xor_sync(0xFFFFFFFF, acc, o);
    __shared__ float red[8];
    if (lane == 0) red[wid] = acc;
    __syncthreads();
    if (t == 0) {
        float tot = 0.f;
        #pragma unroll
        for (int w = 0; w < 8; w++) tot += red[w];
        out[0] = tot / (float)TWO_N;
    }
}

// ---------------- launch ----------------------------------------------------
extern "C" void kernel_launch(void* const* d_in, const int* in_sizes, int n_in,
                              void* d_out, int out_size) {
    const float* z1 = (const float*)d_in[0];
    const float* z2 = (const float*)d_in[1];
    float* out = (float*)d_out;

    cudaFuncSetAttribute(k_gemm, cudaFuncAttributeMaxDynamicSharedMemorySize, SMEM_TOTAL);

    k_prep<<<NROW, 256>>>(z1, z2);
    dim3 grid(TWO_N / TN_TILE, TWO_N / TM_TILE);   // 64 x 64, lower half exits
    k_gemm<<<grid, 256, SMEM_TOTAL>>>();
    k_final<<<1, 256>>>(out);
}

// round 4
// speedup vs baseline: 1.0702x; 1.0702x over previous
#include <cuda_runtime.h>
#include <cuda_bf16.h>
#include <cstdint>
#include <cmath>

#define NROW 4096
#define ZD   2048
#define TWO_N 8192
#define TM_TILE 128
#define TN_TILE 128
#define TKS 64                       // k elems per stage (128B rows)
#define NKSTG (ZD / TKS)             // 32 stages of work
#define STAGES 3
#define STAGE_BYTES (2 * TM_TILE * 128)   // A(16KB) + B(16KB)
#define SMEM_TOTAL (STAGES * STAGE_BYTES) // 96 KB dynamic
#define NTILE 64                     // 8192/128 tiles per dim
#define NUM_TILES ((NTILE * (NTILE + 1)) / 2)   // 2080

// ---------------- scratch (device globals; no allocation allowed) ----------
__device__ __align__(256) __nv_bfloat16 g_reps[(size_t)TWO_N * ZD];   // 32 MB
__device__ float g_rowsum[TWO_N];
__device__ float g_pos[NROW];

// ---------------- helpers ---------------------------------------------------
__device__ __forceinline__ uint32_t smem_u32(const void* p) {
    uint32_t a;
    asm("{ .reg .u64 t; cvta.to.shared.u64 t, %1; cvt.u32.u64 %0, t; }" : "=r"(a) : "l"(p));
    return a;
}
#define SWZ(bo) ((bo) ^ (((bo) >> 3) & 0x70))
#define CP_ASYNC16(dst, src) \
    asm volatile("cp.async.cg.shared.global [%0], [%1], 16;" :: "r"(dst), "l"(src))
#define CP_COMMIT() asm volatile("cp.async.commit_group;" ::: "memory")
#define CP_WAIT1()  asm volatile("cp.async.wait_group 1;" ::: "memory")

__device__ __forceinline__ void ldmatrix_x4(uint32_t& r0, uint32_t& r1,
                                            uint32_t& r2, uint32_t& r3, uint32_t addr) {
    asm volatile("ldmatrix.sync.aligned.m8n8.x4.shared.b16 {%0,%1,%2,%3}, [%4];"
                 : "=r"(r0), "=r"(r1), "=r"(r2), "=r"(r3) : "r"(addr));
}
__device__ __forceinline__ void mma_bf16(float* c, const uint32_t* a, uint32_t b0, uint32_t b1) {
    asm volatile("mma.sync.aligned.m16n8k16.row.col.f32.bf16.bf16.f32 "
                 "{%0,%1,%2,%3}, {%4,%5,%6,%7}, {%8,%9}, {%0,%1,%2,%3};"
                 : "+f"(c[0]), "+f"(c[1]), "+f"(c[2]), "+f"(c[3])
                 : "r"(a[0]), "r"(a[1]), "r"(a[2]), "r"(a[3]), "r"(b0), "r"(b1));
}

// ---------------- kernel 1: normalize + pos + zero rowsum ------------------
__global__ void __launch_bounds__(256) k_prep(const float* __restrict__ z1,
                                              const float* __restrict__ z2) {
    int row = blockIdx.x;
    int t = threadIdx.x, lane = t & 31, wid = t >> 5;
    const float4* p1 = reinterpret_cast<const float4*>(z1) + (size_t)row * (ZD / 4);
    const float4* p2 = reinterpret_cast<const float4*>(z2) + (size_t)row * (ZD / 4);
    float4 a[2], b[2];
    a[0] = p1[2 * t]; a[1] = p1[2 * t + 1];
    b[0] = p2[2 * t]; b[1] = p2[2 * t + 1];
    const float* af = reinterpret_cast<const float*>(a);
    const float* bf = reinterpret_cast<const float*>(b);
    float s1 = 0.f, s2 = 0.f, sd = 0.f;
    #pragma unroll
    for (int i = 0; i < 8; i++) { s1 += af[i] * af[i]; s2 += bf[i] * bf[i]; sd += af[i] * bf[i]; }
    #pragma unroll
    for (int o = 16; o > 0; o >>= 1) {
        s1 += __shfl_xor_sync(0xFFFFFFFF, s1, o);
        s2 += __shfl_xor_sync(0xFFFFFFFF, s2, o);
        sd += __shfl_xor_sync(0xFFFFFFFF, sd, o);
    }
    __shared__ float red[3][8];
    if (lane == 0) { red[0][wid] = s1; red[1][wid] = s2; red[2][wid] = sd; }
    __syncthreads();
    float t1 = 0.f, t2 = 0.f, td = 0.f;
    #pragma unroll
    for (int w = 0; w < 8; w++) { t1 += red[0][w]; t2 += red[1][w]; td += red[2][w]; }
    float r1 = rsqrtf(t1), r2 = rsqrtf(t2);
    if (t == 0) {
        g_pos[row] = td * r1 * r2 * 2.0f;   // /T, T=0.5
        g_rowsum[row] = 0.f;
        g_rowsum[row + NROW] = 0.f;
    }
    __nv_bfloat16 oa[8], ob[8];
    #pragma unroll
    for (int i = 0; i < 8; i++) { oa[i] = __float2bfloat16(af[i] * r1); ob[i] = __float2bfloat16(bf[i] * r2); }
    *reinterpret_cast<uint4*>(g_reps + (size_t)row * ZD + 8 * t)          = *reinterpret_cast<uint4*>(oa);
    *reinterpret_cast<uint4*>(g_reps + (size_t)(row + NROW) * ZD + 8 * t) = *reinterpret_cast<uint4*>(ob);
}

// ---------------- kernel 2: HMMA GEMM (upper triangle) + exp-reduce --------
__global__ void __launch_bounds__(256, 2) k_gemm() {
    // triangular decode: tiles with tn >= tm, ordered by tm
    const int idx = blockIdx.x;
    int tm = (int)((129.0f - sqrtf(129.0f * 129.0f - 8.0f * (float)idx)) * 0.5f);
    if (tm < 0) tm = 0;
    if (tm > NTILE - 1) tm = NTILE - 1;
    // cum(t) = 64t - t(t-1)/2
    while ((NTILE * (tm + 1) - ((tm + 1) * tm) / 2) <= idx) tm++;
    while ((NTILE * tm - (tm * (tm - 1)) / 2) > idx) tm--;
    const int tn = tm + (idx - (NTILE * tm - (tm * (tm - 1)) / 2));
    const bool diag = (tn == tm);

    extern __shared__ unsigned char smem[];
    uint32_t smem_base = smem_u32(smem);
    const int tid = threadIdx.x, lane = tid & 31, wid = tid >> 5;
    const int wm = wid & 1, wn = wid >> 1;    // warp grid 2 (M) x 4 (N)

    const __nv_bfloat16* gA = g_reps + (size_t)(tm * TM_TILE) * ZD;
    const __nv_bfloat16* gB = g_reps + (size_t)(tn * TN_TILE) * ZD;

    // cp.async: thread t -> row (t&127), chunks [cp, cp+3] of 8 (16B each), A and B
    const int lrow_g = tid & 127;
    const int cp = (tid >> 7) * 4;
    uint32_t sdst[4];
    #pragma unroll
    for (int c = 0; c < 4; c++) {
        uint32_t bo = (uint32_t)(lrow_g * 128 + (cp + c) * 16);
        sdst[c] = SWZ(bo);
    }
    const __nv_bfloat16* gArow = gA + (size_t)lrow_g * ZD + cp * 8;
    const __nv_bfloat16* gBrow = gB + (size_t)lrow_g * ZD + cp * 8;

    auto load_stage = [&](int s, int ks) {
        uint32_t sa = smem_base + s * STAGE_BYTES;
        const __nv_bfloat16* a = gArow + ks * TKS;
        const __nv_bfloat16* b = gBrow + ks * TKS;
        #pragma unroll
        for (int c = 0; c < 4; c++) {
            CP_ASYNC16(sa + sdst[c], a + c * 8);
            CP_ASYNC16(sa + 16384 + sdst[c], b + c * 8);
        }
    };

    float acc[4][4][4];
    #pragma unroll
    for (int i = 0; i < 4; i++)
        #pragma unroll
        for (int j = 0; j < 4; j++)
            #pragma unroll
            for (int q = 0; q < 4; q++) acc[i][j][q] = 0.f;

    // prefetch 2 stages
    load_stage(0, 0); CP_COMMIT();
    load_stage(1, 1); CP_COMMIT();

    const int lrow = lane & 15;
    const int lk   = lane >> 4;

    int sidx = 0;
    for (int ks = 0; ks < NKSTG; ks++) {
        CP_WAIT1();
        __syncthreads();
        if (ks + 2 < NKSTG) {
            int ns = sidx + 2; if (ns >= STAGES) ns -= STAGES;
            load_stage(ns, ks + 2);
        }
        CP_COMMIT();

        uint32_t sa = smem_base + sidx * STAGE_BYTES;
        uint32_t sb = sa + 16384;

        #pragma unroll
        for (int kk = 0; kk < 4; kk++) {           // 4 x k16 per stage
            uint32_t afr[4][4];
            #pragma unroll
            for (int i = 0; i < 4; i++) {
                int row = wm * 64 + i * 16 + lrow;
                uint32_t bo = (uint32_t)(row * 128 + (kk * 2 + lk) * 16);
                ldmatrix_x4(afr[i][0], afr[i][1], afr[i][2], afr[i][3], sa + SWZ(bo));
            }
            uint32_t bfr[2][4];
            #pragma unroll
            for (int h = 0; h < 2; h++) {
                int row = wn * 32 + h * 16 + lrow;
                uint32_t bo = (uint32_t)(row * 128 + (kk * 2 + lk) * 16);
                ldmatrix_x4(bfr[h][0], bfr[h][1], bfr[h][2], bfr[h][3], sb + SWZ(bo));
            }
            #pragma unroll
            for (int i = 0; i < 4; i++) {
                #pragma unroll
                for (int j = 0; j < 4; j++) {
                    uint32_t b0 = bfr[j >> 1][j & 1];
                    uint32_t b1 = bfr[j >> 1][(j & 1) + 2];
                    mma_bf16(acc[i][j], afr[i], b0, b1);
                }
            }
        }
        sidx++; if (sidx >= STAGES) sidx = 0;
    }

    // ---------------- epilogue: exp(2s), mask diag, row+col reduce ----------
    const int rowbase = tm * TM_TILE + wm * 64;
    const int colbase = tn * TN_TILE + wn * 32;
    float rsum[4][2];
    float csum[4][2];
    #pragma unroll
    for (int i = 0; i < 4; i++) { rsum[i][0] = 0.f; rsum[i][1] = 0.f; }
    #pragma unroll
    for (int j = 0; j < 4; j++) { csum[j][0] = 0.f; csum[j][1] = 0.f; }

    #pragma unroll
    for (int i = 0; i < 4; i++) {
        #pragma unroll
        for (int j = 0; j < 4; j++) {
            #pragma unroll
            for (int q = 0; q < 4; q++) {
                int h = q >> 1, c = q & 1;
                float e = __expf(2.0f * acc[i][j][q]);   // logits = s / T, T=0.5
                if (diag) {
                    int grow = rowbase + i * 16 + (lane >> 2) + h * 8;
                    int gcol = colbase + j * 8 + (lane & 3) * 2 + c;
                    if (grow == gcol) e = 0.f;
                }
                rsum[i][h] += e;
                csum[j][c] += e;
            }
        }
    }
    #pragma unroll
    for (int i = 0; i < 4; i++) {
        #pragma unroll
        for (int h = 0; h < 2; h++) {
            float v = rsum[i][h];
            v += __shfl_xor_sync(0xFFFFFFFF, v, 1);
            v += __shfl_xor_sync(0xFFFFFFFF, v, 2);
            if ((lane & 3) == 0)
                atomicAdd(&g_rowsum[rowbase + i * 16 + (lane >> 2) + h * 8], v);
        }
    }
    if (!diag) {
        #pragma unroll
        for (int j = 0; j < 4; j++) {
            #pragma unroll
            for (int c = 0; c < 2; c++) {
                float v = csum[j][c];
                v += __shfl_xor_sync(0xFFFFFFFF, v, 4);
                v += __shfl_xor_sync(0xFFFFFFFF, v, 8);
                v += __shfl_xor_sync(0xFFFFFFFF, v, 16);
                if (lane < 4)
                    atomicAdd(&g_rowsum[colbase + j * 8 + lane * 2 + c], v);
            }
        }
    }
}

// ---------------- kernel 3: final reduction --------------------------------
__global__ void __launch_bounds__(256) k_final(float* __restrict__ out) {
    int t = threadIdx.x, lane = t & 31, wid = t >> 5;
    float acc = 0.f;
    for (int r = t; r < TWO_N; r += 256)
        acc += logf(g_rowsum[r]) - g_pos[r & (NROW - 1)];
    #pragma unroll
    for (int o = 16; o > 0; o >>= 1) acc += __shfl_xor_sync(0xFFFFFFFF, acc, o);
    __shared__ float red[8];
    if (lane == 0) red[wid] = acc;
    __syncthreads();
    if (t == 0) {
        float tot = 0.f;
        #pragma unroll
        for (int w = 0; w < 8; w++) tot += red[w];
        out[0] = tot / (float)TWO_N;
    }
}

// ---------------- launch ----------------------------------------------------
extern "C" void kernel_launch(void* const* d_in, const int* in_sizes, int n_in,
                              void* d_out, int out_size) {
    const float* z1 = (const float*)d_in[0];
    const float* z2 = (const float*)d_in[1];
    float* out = (float*)d_out;

    cudaFuncSetAttribute(k_gemm, cudaFuncAttributeMaxDynamicSharedMemorySize, SMEM_TOTAL);

    k_prep<<<NROW, 256>>>(z1, z2);
    k_gemm<<<NUM_TILES, 256, SMEM_TOTAL>>>();
    k_final<<<1, 256>>>(out);
}

// round 5
// speedup vs baseline: 1.3210x; 1.2344x over previous
#include <cuda_runtime.h>
#include <cuda_bf16.h>
#include <cstdint>
#include <cmath>

#define NROW 4096
#define ZD   2048
#define TWO_N 8192
#define TM_TILE 128
#define TN_TILE 128
#define TKS 128                      // fp8 elems per stage = 128 B rows
#define NKSTG (ZD / TKS)             // 16 stages
#define STAGES 3
#define STAGE_BYTES (2 * TM_TILE * 128)   // A(16KB) + B(16KB)
#define SMEM_TOTAL (STAGES * STAGE_BYTES) // 96 KB dynamic
#define NTILE 64
#define NUM_TILES ((NTILE * (NTILE + 1)) / 2)   // 2080
#define FP8_SCALE 16.0f
// logits = 2 * (acc / (16*16)) = acc / 128
#define EPI_SCALE 0.0078125f

// ---------------- scratch ----------------------------------------------------
__device__ __align__(256) uint8_t g_reps[(size_t)TWO_N * ZD];   // 16 MB e4m3
__device__ float g_rowsum[TWO_N];
__device__ float g_pos[NROW];

// ---------------- helpers ----------------------------------------------------
__device__ __forceinline__ uint32_t smem_u32(const void* p) {
    uint32_t a;
    asm("{ .reg .u64 t; cvta.to.shared.u64 t, %1; cvt.u32.u64 %0, t; }" : "=r"(a) : "l"(p));
    return a;
}
#define SWZ(bo) ((bo) ^ (((bo) >> 3) & 0x70))
#define CP_ASYNC16(dst, src) \
    asm volatile("cp.async.cg.shared.global [%0], [%1], 16;" :: "r"(dst), "l"(src))
#define CP_COMMIT() asm volatile("cp.async.commit_group;" ::: "memory")
#define CP_WAIT1()  asm volatile("cp.async.wait_group 1;" ::: "memory")

__device__ __forceinline__ void ldmatrix_x4(uint32_t& r0, uint32_t& r1,
                                            uint32_t& r2, uint32_t& r3, uint32_t addr) {
    asm volatile("ldmatrix.sync.aligned.m8n8.x4.shared.b16 {%0,%1,%2,%3}, [%4];"
                 : "=r"(r0), "=r"(r1), "=r"(r2), "=r"(r3) : "r"(addr));
}
__device__ __forceinline__ void mma_fp8(float* c, const uint32_t* a, uint32_t b0, uint32_t b1) {
    asm volatile("mma.sync.aligned.m16n8k32.row.col.f32.e4m3.e4m3.f32 "
                 "{%0,%1,%2,%3}, {%4,%5,%6,%7}, {%8,%9}, {%0,%1,%2,%3};"
                 : "+f"(c[0]), "+f"(c[1]), "+f"(c[2]), "+f"(c[3])
                 : "r"(a[0]), "r"(a[1]), "r"(a[2]), "r"(a[3]), "r"(b0), "r"(b1));
}
__device__ __forceinline__ uint16_t cvt_e4m3x2(float hi, float lo) {
    uint16_t d;
    asm("cvt.rn.satfinite.e4m3x2.f32 %0, %1, %2;" : "=h"(d) : "f"(hi), "f"(lo));
    return d;   // low byte = lo, high byte = hi
}

// ---------------- kernel 1: normalize + pos + fp8 quantize -----------------
__global__ void __launch_bounds__(256) k_prep(const float* __restrict__ z1,
                                              const float* __restrict__ z2) {
    int row = blockIdx.x;
    int t = threadIdx.x, lane = t & 31, wid = t >> 5;
    const float4* p1 = reinterpret_cast<const float4*>(z1) + (size_t)row * (ZD / 4);
    const float4* p2 = reinterpret_cast<const float4*>(z2) + (size_t)row * (ZD / 4);
    float4 a[2], b[2];
    a[0] = p1[2 * t]; a[1] = p1[2 * t + 1];
    b[0] = p2[2 * t]; b[1] = p2[2 * t + 1];
    const float* af = reinterpret_cast<const float*>(a);
    const float* bf = reinterpret_cast<const float*>(b);
    float s1 = 0.f, s2 = 0.f, sd = 0.f;
    #pragma unroll
    for (int i = 0; i < 8; i++) { s1 += af[i] * af[i]; s2 += bf[i] * bf[i]; sd += af[i] * bf[i]; }
    #pragma unroll
    for (int o = 16; o > 0; o >>= 1) {
        s1 += __shfl_xor_sync(0xFFFFFFFF, s1, o);
        s2 += __shfl_xor_sync(0xFFFFFFFF, s2, o);
        sd += __shfl_xor_sync(0xFFFFFFFF, sd, o);
    }
    __shared__ float red[3][8];
    if (lane == 0) { red[0][wid] = s1; red[1][wid] = s2; red[2][wid] = sd; }
    __syncthreads();
    float t1 = 0.f, t2 = 0.f, td = 0.f;
    #pragma unroll
    for (int w = 0; w < 8; w++) { t1 += red[0][w]; t2 += red[1][w]; td += red[2][w]; }
    float r1 = rsqrtf(t1) * FP8_SCALE, r2 = rsqrtf(t2) * FP8_SCALE;
    if (t == 0) {
        g_pos[row] = td * rsqrtf(t1) * rsqrtf(t2) * 2.0f;   // /T, T=0.5 (exact fp32)
        g_rowsum[row] = 0.f;
        g_rowsum[row + NROW] = 0.f;
    }
    uint16_t qa[4], qb[4];
    #pragma unroll
    for (int i = 0; i < 4; i++) {
        qa[i] = cvt_e4m3x2(af[2 * i + 1] * r1, af[2 * i] * r1);
        qb[i] = cvt_e4m3x2(bf[2 * i + 1] * r2, bf[2 * i] * r2);
    }
    uint2 va, vb;
    va.x = (uint32_t)qa[0] | ((uint32_t)qa[1] << 16);
    va.y = (uint32_t)qa[2] | ((uint32_t)qa[3] << 16);
    vb.x = (uint32_t)qb[0] | ((uint32_t)qb[1] << 16);
    vb.y = (uint32_t)qb[2] | ((uint32_t)qb[3] << 16);
    *reinterpret_cast<uint2*>(g_reps + (size_t)row * ZD + 8 * t)          = va;
    *reinterpret_cast<uint2*>(g_reps + (size_t)(row + NROW) * ZD + 8 * t) = vb;
}

// ---------------- kernel 2: FP8 MMA GEMM (upper triangle) + exp-reduce -----
__global__ void __launch_bounds__(256, 2) k_gemm() {
    const int idx = blockIdx.x;
    int tm = (int)((129.0f - sqrtf(129.0f * 129.0f - 8.0f * (float)idx)) * 0.5f);
    if (tm < 0) tm = 0;
    if (tm > NTILE - 1) tm = NTILE - 1;
    while ((NTILE * (tm + 1) - ((tm + 1) * tm) / 2) <= idx) tm++;
    while ((NTILE * tm - (tm * (tm - 1)) / 2) > idx) tm--;
    const int tn = tm + (idx - (NTILE * tm - (tm * (tm - 1)) / 2));
    const bool diag = (tn == tm);

    extern __shared__ unsigned char smem[];
    uint32_t smem_base = smem_u32(smem);
    const int tid = threadIdx.x, lane = tid & 31, wid = tid >> 5;
    const int wm = wid & 1, wn = wid >> 1;    // warp grid 2 (M) x 4 (N), warp tile 64x32

    const uint8_t* gA = g_reps + (size_t)(tm * TM_TILE) * ZD;
    const uint8_t* gB = g_reps + (size_t)(tn * TN_TILE) * ZD;

    // cp.async: thread -> row (tid&127), chunks cp..cp+3 (16B each)
    const int lrow_g = tid & 127;
    const int cp = (tid >> 7) * 4;
    uint32_t sdst[4];
    #pragma unroll
    for (int c = 0; c < 4; c++) {
        uint32_t bo = (uint32_t)(lrow_g * 128 + (cp + c) * 16);
        sdst[c] = SWZ(bo);
    }
    const uint8_t* gArow = gA + (size_t)lrow_g * ZD + cp * 16;
    const uint8_t* gBrow = gB + (size_t)lrow_g * ZD + cp * 16;

    auto load_stage = [&](int s, int ks) {
        uint32_t sa = smem_base + s * STAGE_BYTES;
        const uint8_t* a = gArow + ks * TKS;
        const uint8_t* b = gBrow + ks * TKS;
        #pragma unroll
        for (int c = 0; c < 4; c++) {
            CP_ASYNC16(sa + sdst[c], a + c * 16);
            CP_ASYNC16(sa + 16384 + sdst[c], b + c * 16);
        }
    };

    float acc[4][4][4];
    #pragma unroll
    for (int i = 0; i < 4; i++)
        #pragma unroll
        for (int j = 0; j < 4; j++)
            #pragma unroll
            for (int q = 0; q < 4; q++) acc[i][j][q] = 0.f;

    load_stage(0, 0); CP_COMMIT();
    load_stage(1, 1); CP_COMMIT();

    // ldmatrix lane address components (fp8 k32 fragments)
    const int arow_l = ((lane >> 3) & 1) * 8 + (lane & 7);   // + wm*64 + i*16
    const int abyte_l = ((lane >> 4) & 1) * 16;              // + kk*32
    const int brow_l = ((lane >> 4) & 1) * 8 + (lane & 7);   // + wn*32 + p*16
    const int bbyte_l = ((lane >> 3) & 1) * 16;              // + kk*32

    int sidx = 0;
    for (int ks = 0; ks < NKSTG; ks++) {
        CP_WAIT1();
        __syncthreads();
        if (ks + 2 < NKSTG) {
            int ns = sidx + 2; if (ns >= STAGES) ns -= STAGES;
            load_stage(ns, ks + 2);
        }
        CP_COMMIT();

        uint32_t sa = smem_base + sidx * STAGE_BYTES;
        uint32_t sb = sa + 16384;

        #pragma unroll
        for (int kk = 0; kk < 4; kk++) {           // 4 x k32 per stage
            uint32_t afr[4][4];
            #pragma unroll
            for (int i = 0; i < 4; i++) {
                int row = wm * 64 + i * 16 + arow_l;
                uint32_t bo = (uint32_t)(row * 128 + kk * 32 + abyte_l);
                ldmatrix_x4(afr[i][0], afr[i][1], afr[i][2], afr[i][3], sa + SWZ(bo));
            }
            uint32_t bfr[2][4];                    // p=0: n8 groups 0,1 ; p=1: groups 2,3
            #pragma unroll
            for (int p = 0; p < 2; p++) {
                int row = wn * 32 + p * 16 + brow_l;
                uint32_t bo = (uint32_t)(row * 128 + kk * 32 + bbyte_l);
                ldmatrix_x4(bfr[p][0], bfr[p][1], bfr[p][2], bfr[p][3], sb + SWZ(bo));
            }
            #pragma unroll
            for (int i = 0; i < 4; i++) {
                #pragma unroll
                for (int j = 0; j < 4; j++) {
                    uint32_t b0 = bfr[j >> 1][(j & 1) * 2];
                    uint32_t b1 = bfr[j >> 1][(j & 1) * 2 + 1];
                    mma_fp8(acc[i][j], afr[i], b0, b1);
                }
            }
        }
        sidx++; if (sidx >= STAGES) sidx = 0;
    }

    // ---------------- epilogue: exp(acc/128), mask diag, row+col reduce -----
    const int rowbase = tm * TM_TILE + wm * 64;
    const int colbase = tn * TN_TILE + wn * 32;
    float rsum[4][2];
    float csum[4][2];
    #pragma unroll
    for (int i = 0; i < 4; i++) { rsum[i][0] = 0.f; rsum[i][1] = 0.f; }
    #pragma unroll
    for (int j = 0; j < 4; j++) { csum[j][0] = 0.f; csum[j][1] = 0.f; }

    #pragma unroll
    for (int i = 0; i < 4; i++) {
        #pragma unroll
        for (int j = 0; j < 4; j++) {
            #pragma unroll
            for (int q = 0; q < 4; q++) {
                int h = q >> 1, c = q & 1;
                float e = __expf(EPI_SCALE * acc[i][j][q]);
                if (diag) {
                    int grow = rowbase + i * 16 + (lane >> 2) + h * 8;
                    int gcol = colbase + j * 8 + (lane & 3) * 2 + c;
                    if (grow == gcol) e = 0.f;
                }
                rsum[i][h] += e;
                csum[j][c] += e;
            }
        }
    }
    #pragma unroll
    for (int i = 0; i < 4; i++) {
        #pragma unroll
        for (int h = 0; h < 2; h++) {
            float v = rsum[i][h];
            v += __shfl_xor_sync(0xFFFFFFFF, v, 1);
            v += __shfl_xor_sync(0xFFFFFFFF, v, 2);
            if ((lane & 3) == 0)
                atomicAdd(&g_rowsum[rowbase + i * 16 + (lane >> 2) + h * 8], v);
        }
    }
    if (!diag) {
        #pragma unroll
        for (int j = 0; j < 4; j++) {
            #pragma unroll
            for (int c = 0; c < 2; c++) {
                float v = csum[j][c];
                v += __shfl_xor_sync(0xFFFFFFFF, v, 4);
                v += __shfl_xor_sync(0xFFFFFFFF, v, 8);
                v += __shfl_xor_sync(0xFFFFFFFF, v, 16);
                if (lane < 4)
                    atomicAdd(&g_rowsum[colbase + j * 8 + lane * 2 + c], v);
            }
        }
    }
}

// ---------------- kernel 3: final reduction --------------------------------
__global__ void __launch_bounds__(256) k_final(float* __restrict__ out) {
    int t = threadIdx.x, lane = t & 31, wid = t >> 5;
    float acc = 0.f;
    for (int r = t; r < TWO_N; r += 256)
        acc += logf(g_rowsum[r]) - g_pos[r & (NROW - 1)];
    #pragma unroll
    for (int o = 16; o > 0; o >>= 1) acc += __shfl_xor_sync(0xFFFFFFFF, acc, o);
    __shared__ float red[8];
    if (lane == 0) red[wid] = acc;
    __syncthreads();
    if (t == 0) {
        float tot = 0.f;
        #pragma unroll
        for (int w = 0; w < 8; w++) tot += red[w];
        out[0] = tot / (float)TWO_N;
    }
}

// ---------------- launch ----------------------------------------------------
extern "C" void kernel_launch(void* const* d_in, const int* in_sizes, int n_in,
                              void* d_out, int out_size) {
    const float* z1 = (const float*)d_in[0];
    const float* z2 = (const float*)d_in[1];
    float* out = (float*)d_out;

    cudaFuncSetAttribute(k_gemm, cudaFuncAttributeMaxDynamicSharedMemorySize, SMEM_TOTAL);

    k_prep<<<NROW, 256>>>(z1, z2);
    k_gemm<<<NUM_TILES, 256, SMEM_TOTAL>>>();
    k_final<<<1, 256>>>(out);
}